// round 11
// baseline (speedup 1.0000x reference)
#include <cuda_runtime.h>
#include <cstdint>
#include <math.h>

#define N_NODES 50000
#define N_EDGES 640000
#define NH (N_NODES * 128)
#define NB 196  // ceil(N_NODES / 256)

// ---------------- scratch (static device globals) ---------------------------
// INVARIANT: g_indeg and g_cursor are zero at the start of every kernel_launch
// call: zero-initialized at module load; scan_bc re-zeros g_indeg after
// consuming it and zeroes g_cursor before fill uses it, every run.
__device__ uint32_t g_hhb[NH / 2];    // Hs @ gcn_w (unscaled), bf16x2 packed
__device__ uint32_t g_Wc[4 * 16384];  // tf32 weights: gate i, c, o, gcn_w
__device__ int   g_indeg[N_NODES];
__device__ float g_dg[N_NODES];       // rsqrt(1 + indeg)
__device__ int   g_off[N_NODES + 1];
__device__ int   g_cursor[N_NODES];
__device__ int   g_csr[N_EDGES];
__device__ int   g_part[256];
// fused per-channel constants
__device__ float g_cb0[128], g_cb1[128], g_cb2[128], g_wc2[128];
__device__ float g_fa[128];
__device__ float g_fc;

// ---------------- helpers ----------------------------------------------------
__device__ __forceinline__ float tanhfast(float x) {
    float r; asm("tanh.approx.f32 %0, %1;" : "=f"(r) : "f"(x)); return r;
}
__device__ __forceinline__ float sigfast(float x) {
    return 0.5f * tanhfast(0.5f * x) + 0.5f;
}
__device__ __forceinline__ uint32_t to_tf32(float x) {
    uint32_t u; asm("cvt.rna.tf32.f32 %0, %1;" : "=r"(u) : "f"(x)); return u;
}
__device__ __forceinline__ uint32_t pack_bf16x2(float hi, float lo) {
    uint32_t u; asm("cvt.rn.bf16x2.f32 %0, %1, %2;" : "=r"(u) : "f"(hi), "f"(lo)); return u;
}
__device__ __forceinline__ float bf_lo(uint32_t u) { return __uint_as_float(u << 16); }
__device__ __forceinline__ float bf_hi(uint32_t u) { return __uint_as_float(u & 0xffff0000u); }
__device__ __forceinline__ void mma_tf32(float* d, const uint32_t* a, uint32_t b0, uint32_t b1) {
    asm volatile(
        "mma.sync.aligned.m16n8k8.row.col.f32.tf32.tf32.f32 "
        "{%0,%1,%2,%3}, {%4,%5,%6,%7}, {%8,%9}, {%0,%1,%2,%3};"
        : "+f"(d[0]), "+f"(d[1]), "+f"(d[2]), "+f"(d[3])
        : "r"(a[0]), "r"(a[1]), "r"(a[2]), "r"(a[3]), "r"(b0), "r"(b1));
}
__device__ __forceinline__ uint32_t smem_u32(const void* p) {
    uint32_t a;
    asm("{ .reg .u64 t; cvta.to.shared.u64 t, %1; cvt.u32.u64 %0, t; }" : "=r"(a) : "l"(p));
    return a;
}
__device__ __forceinline__ void cp_async16(uint32_t daddr, const void* saddr, int srcsz) {
    asm volatile("cp.async.cg.shared.global [%0], [%1], 16, %2;"
                 :: "r"(daddr), "l"(saddr), "r"(srcsz) : "memory");
}

// ---------------- prep: weights->tf32 + per-channel constants ----------------
__global__ void prep_all(const float* __restrict__ Wx, const float* __restrict__ gcn,
                         const float* __restrict__ theta_b, const float* __restrict__ b,
                         const float* __restrict__ w_c,
                         const float* __restrict__ gamma, const float* __restrict__ beta,
                         const float* __restrict__ mean, const float* __restrict__ var,
                         const float* __restrict__ lin_w, const float* __restrict__ lin_b) {
    if (blockIdx.x < 256) {
        int i = blockIdx.x * 256 + threadIdx.x;   // 0..65535
        int m = i >> 14, r = i & 16383;
        const float* S = (m == 0) ? Wx
                       : (m == 1) ? Wx + 2 * 16384
                       : (m == 2) ? Wx + 3 * 16384 : gcn;
        g_Wc[i] = to_tf32(S[r]);
        return;
    }
    int ch = threadIdx.x;
    if (ch >= 128) return;
    g_cb0[ch] = theta_b[ch] + b[ch];
    g_cb1[ch] = theta_b[256 + ch] + b[256 + ch];
    g_cb2[ch] = theta_b[384 + ch] + b[384 + ch];
    g_wc2[ch] = w_c[256 + ch];
    float sc = gamma[ch] * rsqrtf(var[ch] + 1e-5f);
    g_fa[ch] = sc * lin_w[ch];
    __shared__ float red[128];
    red[ch] = (beta[ch] - mean[ch] * sc) * lin_w[ch];
    __syncthreads();
    for (int o = 64; o > 0; o >>= 1) { if (ch < o) red[ch] += red[ch + o]; __syncthreads(); }
    if (ch == 0) g_fc = red[0] + lin_b[0];
}

__global__ void count_kernel(const int* __restrict__ dst) {
    int e = blockIdx.x * blockDim.x + threadIdx.x;
    if (e < N_EDGES) atomicAdd(&g_indeg[dst[e]], 1);
}

// ---- scan stage A: per-block partial sums ----
__global__ __launch_bounds__(256) void scan_a() {
    int i = blockIdx.x * 256 + threadIdx.x;
    int v = (i < N_NODES) ? g_indeg[i] : 0;
    int lane = threadIdx.x & 31, warp = threadIdx.x >> 5;
#pragma unroll
    for (int o = 16; o > 0; o >>= 1) v += __shfl_down_sync(0xffffffffu, v, o);
    __shared__ int ws[8];
    if (lane == 0) ws[warp] = v;
    __syncthreads();
    if (threadIdx.x == 0) {
        int s = 0;
#pragma unroll
        for (int w = 0; w < 8; w++) s += ws[w];
        g_part[blockIdx.x] = s;
    }
}
// ---- scan stage BC: re-scan partials + local scan; zero indeg after use ----
__global__ __launch_bounds__(256) void scan_bc() {
    int t = threadIdx.x, lane = t & 31, warp = t >> 5;
    __shared__ int s2[256];
    __shared__ int ws[8];
    {
        int v = (t < NB) ? g_part[t] : 0;
        int x = v;
#pragma unroll
        for (int o = 1; o < 32; o <<= 1) {
            int y = __shfl_up_sync(0xffffffffu, x, o);
            if (lane >= o) x += y;
        }
        if (lane == 31) ws[warp] = x;
        __syncthreads();
        if (warp == 0 && lane < 8) {
            int w = ws[lane];
#pragma unroll
            for (int o = 1; o < 8; o <<= 1) {
                int y = __shfl_up_sync(0xffu, w, o);
                if (lane >= o) w += y;
            }
            ws[lane] = w;
        }
        __syncthreads();
        s2[t] = x + (warp > 0 ? ws[warp - 1] : 0);
        __syncthreads();
    }
    int blockbase = (blockIdx.x == 0) ? 0 : s2[blockIdx.x - 1];
    __syncthreads();
    int i = blockIdx.x * 256 + t;
    int v = (i < N_NODES) ? g_indeg[i] : 0;
    int x = v;
#pragma unroll
    for (int o = 1; o < 32; o <<= 1) {
        int y = __shfl_up_sync(0xffffffffu, x, o);
        if (lane >= o) x += y;
    }
    if (lane == 31) ws[warp] = x;
    __syncthreads();
    if (warp == 0 && lane < 8) {
        int w = ws[lane];
#pragma unroll
        for (int o = 1; o < 8; o <<= 1) {
            int y = __shfl_up_sync(0xffu, w, o);
            if (lane >= o) w += y;
        }
        ws[lane] = w;
    }
    __syncthreads();
    if (i < N_NODES) {
        g_off[i] = x - v + (warp > 0 ? ws[warp - 1] : 0) + blockbase;
        g_dg[i] = rsqrtf(1.0f + (float)v);
        g_cursor[i] = 0;
        g_indeg[i] = 0;  // restore invariant for next replay
    }
    if (blockIdx.x == 0 && t == 0) g_off[N_NODES] = N_EDGES;
}

__global__ void fill_kernel(const int* __restrict__ src, const int* __restrict__ dst) {
    int e = blockIdx.x * blockDim.x + threadIdx.x;
    if (e >= N_EDGES) return;
    int d = dst[e];
    g_csr[g_off[d] + atomicAdd(&g_cursor[d], 1)] = src[e];
}

// ============================================================================
// Fully fused GEMM, spill-free target: 512 threads, 16 warps (4m x 4n),
// warp tile 32x32 -> 96 accumulator regs (NG=3).
// A loaded RAW fp32 via cp.async; cvt.rna applied at fragment-load time.
// Epilogue constants staged in smem. Hs stored tf32 in smem for phase 2.
// smem u32: [0]=A/Hs-c0 (8704), [1]=B_i/Hs-c1, [2]=B_c/gcnw-c0,
//           [3]=B_o/gcnw-c1, [34816..35328)=constants cb0|cb1|cb2|wc2
// ============================================================================
#define SMC 34816
#define SMU (34816 + 512)

__global__ __launch_bounds__(512, 1) void gemm_fused(
    const float* __restrict__ A, const uint32_t* __restrict__ W,
    uint32_t* __restrict__ out, int M)
{
    extern __shared__ uint32_t sm[];
    const int tid = threadIdx.x, lane = tid & 31;
    const int wid = tid >> 5, wm = wid >> 2, wn = wid & 3;
    const int q = lane >> 2, r = lane & 3;
    const int rowblk = blockIdx.x * 128;
    const uint32_t sbase = smem_u32(sm);

    // stage epilogue constants (512 floats) into smem
    {
        int a = tid >> 7, c = tid & 127;
        float v = (a == 0) ? g_cb0[c] : (a == 1) ? g_cb1[c]
                : (a == 2) ? g_cb2[c] : g_wc2[c];
        sm[SMC + tid] = __float_as_uint(v);
    }

    float C[3][2][4][4];
#pragma unroll
    for (int g = 0; g < 3; g++)
#pragma unroll
        for (int i = 0; i < 2; i++)
#pragma unroll
            for (int j = 0; j < 4; j++)
#pragma unroll
                for (int k = 0; k < 4; k++) C[g][i][j][k] = 0.0f;

    // ================= phase 1: z = x @ W_gate for 3 gates =================
#pragma unroll
    for (int chunk = 0; chunk < 2; chunk++) {
        const int k0 = chunk * 64;
        if (chunk) __syncthreads();
        // B gates via cp.async: 3 x 2048 float4, 12 per thread
#pragma unroll
        for (int g = 0; g < 3; g++) {
#pragma unroll
            for (int t = 0; t < 4; t++) {
                int i = tid + t * 512;
                int row = i >> 5, j = i & 31;
                cp_async16(sbase + (8704 * (1 + g) + row * 136 + j * 4) * 4,
                           W + (size_t)g * 16384 + (size_t)(k0 + row) * 128 + j * 4, 16);
            }
        }
        // A raw fp32 via cp.async: 2048 float4, 4 per thread
#pragma unroll
        for (int t = 0; t < 4; t++) {
            int i = tid + t * 512;
            int row = i >> 4, j = i & 15;
            int gr = rowblk + row;
            cp_async16(sbase + (row * 68 + j * 4) * 4,
                       A + (size_t)gr * 128 + k0 + j * 4,
                       (gr < M) ? 16 : 0);
        }
        asm volatile("cp.async.commit_group;" ::: "memory");
        asm volatile("cp.async.wait_group 0;" ::: "memory");
        __syncthreads();

#pragma unroll
        for (int ks = 0; ks < 8; ks++) {
            const int kb = ks * 8;
            uint32_t a[2][4];
#pragma unroll
            for (int ma = 0; ma < 2; ma++) {
                int m = wm * 32 + ma * 16 + q;
                const uint32_t* ap = &sm[m * 68 + kb + r];
                a[ma][0] = to_tf32(__uint_as_float(ap[0]));
                a[ma][2] = to_tf32(__uint_as_float(ap[4]));
                a[ma][1] = to_tf32(__uint_as_float(ap[8 * 68]));
                a[ma][3] = to_tf32(__uint_as_float(ap[8 * 68 + 4]));
            }
#pragma unroll
            for (int g = 0; g < 3; g++) {
                const uint32_t* bs = sm + 8704 * (1 + g);
#pragma unroll
                for (int na = 0; na < 4; na++) {
                    int n = wn * 32 + na * 8 + q;
                    const uint32_t* bp = &bs[(kb + r) * 136 + n];
                    uint32_t b0 = bp[0], b1 = bp[4 * 136];
#pragma unroll
                    for (int ma = 0; ma < 2; ma++) mma_tf32(C[g][ma][na], a[ma], b0, b1);
                }
            }
        }
    }
    __syncthreads();  // all reads of A/B done before overwrite

    // gcn_w loads into bufs 2,3 (overlap LSTM epilogue math): 8 per thread
#pragma unroll
    for (int t = 0; t < 8; t++) {
        int i = tid + t * 512;
        int chunk = i >> 11;
        int rj = i & 2047;
        int row = rj >> 5, j = rj & 31;
        cp_async16(sbase + (8704 * (2 + chunk) + row * 136 + j * 4) * 4,
                   W + 3 * 16384 + (size_t)(chunk * 64 + row) * 128 + j * 4, 16);
    }
    asm volatile("cp.async.commit_group;" ::: "memory");

    // ============ LSTM epilogue -> Hs (tf32 bits) into smem bufs 0,1 ========
#pragma unroll
    for (int ma = 0; ma < 2; ma++) {
#pragma unroll
        for (int half = 0; half < 2; half++) {
            int lrow = wm * 32 + ma * 16 + q + half * 8;
#pragma unroll
            for (int na = 0; na < 4; na++) {
                int ch = wn * 32 + na * 8 + 2 * r;
                uint2 h2;
                {
                    float zi = C[0][ma][na][half * 2] + __uint_as_float(sm[SMC + ch]);
                    float zc = C[1][ma][na][half * 2] + __uint_as_float(sm[SMC + 128 + ch]);
                    float zo = C[2][ma][na][half * 2] + __uint_as_float(sm[SMC + 256 + ch]);
                    float I = sigfast(zi);
                    float T = tanhfast(zc);
                    float Cs = I * T;
                    float O = sigfast(zo + __uint_as_float(sm[SMC + 384 + ch]) * Cs);
                    h2.x = to_tf32(O * tanhfast(Cs));
                }
                {
                    float zi = C[0][ma][na][half * 2 + 1] + __uint_as_float(sm[SMC + ch + 1]);
                    float zc = C[1][ma][na][half * 2 + 1] + __uint_as_float(sm[SMC + 129 + ch]);
                    float zo = C[2][ma][na][half * 2 + 1] + __uint_as_float(sm[SMC + 257 + ch]);
                    float I = sigfast(zi);
                    float T = tanhfast(zc);
                    float Cs = I * T;
                    float O = sigfast(zo + __uint_as_float(sm[SMC + 385 + ch]) * Cs);
                    h2.y = to_tf32(O * tanhfast(Cs));
                }
                int cchunk = ch >> 6, col = ch & 63;
                *(uint2*)(&sm[cchunk * 8704 + lrow * 68 + col]) = h2;
            }
        }
    }
    asm volatile("cp.async.wait_group 0;" ::: "memory");
    __syncthreads();

    // ================= phase 2: hh = Hs @ gcn_w =============================
    float D[2][4][4];
#pragma unroll
    for (int i = 0; i < 2; i++)
#pragma unroll
        for (int j = 0; j < 4; j++)
#pragma unroll
            for (int k = 0; k < 4; k++) D[i][j][k] = 0.0f;

#pragma unroll
    for (int chunk = 0; chunk < 2; chunk++) {
        const uint32_t* as = sm + chunk * 8704;
        const uint32_t* bs = sm + (2 + chunk) * 8704;
#pragma unroll
        for (int ks = 0; ks < 8; ks++) {
            const int kb = ks * 8;
            uint32_t a[2][4];
#pragma unroll
            for (int ma = 0; ma < 2; ma++) {
                int m = wm * 32 + ma * 16 + q;
                const uint32_t* ap = &as[m * 68 + kb + r];
                a[ma][0] = ap[0];
                a[ma][2] = ap[4];
                a[ma][1] = ap[8 * 68];
                a[ma][3] = ap[8 * 68 + 4];
            }
#pragma unroll
            for (int na = 0; na < 4; na++) {
                int n = wn * 32 + na * 8 + q;
                const uint32_t* bp = &bs[(kb + r) * 136 + n];
                uint32_t b0 = bp[0], b1 = bp[4 * 136];
#pragma unroll
                for (int ma = 0; ma < 2; ma++) mma_tf32(D[ma][na], a[ma], b0, b1);
            }
        }
    }

    // ---- epilogue 2: write hh as bf16x2 ----
#pragma unroll
    for (int ma = 0; ma < 2; ma++) {
#pragma unroll
        for (int half = 0; half < 2; half++) {
            int row = rowblk + wm * 32 + ma * 16 + q + half * 8;
            if (row >= M) continue;
#pragma unroll
            for (int na = 0; na < 4; na++) {
                int ch = wn * 32 + na * 8 + 2 * r;
                out[(size_t)row * 64 + (ch >> 1)] =
                    pack_bf16x2(D[ma][na][half * 2 + 1], D[ma][na][half * 2]);
            }
        }
    }
}

// ============================================================================
// gather + finalize: warp per node, bf16 hh; cnt from CSR offsets
// ============================================================================
__global__ __launch_bounds__(256) void gather_finalize(const float* __restrict__ gcn_b,
                                                       float* __restrict__ out)
{
    int node = (blockIdx.x * blockDim.x + threadIdx.x) >> 5;
    int lane = threadIdx.x & 31;
    if (node >= N_NODES) return;
    int base = g_off[node];
    int cnt = g_off[node + 1] - base;
    float dgi = g_dg[node];

    const uint2* hh2 = (const uint2*)g_hhb;
    uint2 hv = hh2[(size_t)node * 32 + lane];
    float a0 = dgi * bf_lo(hv.x), a1 = dgi * bf_hi(hv.x);
    float a2 = dgi * bf_lo(hv.y), a3 = dgi * bf_hi(hv.y);

    for (int e0 = 0; e0 < cnt; e0 += 32) {
        int myidx = (e0 + lane < cnt) ? g_csr[base + e0 + lane] : 0;
        int lim = min(32, cnt - e0);
        int t = 0;
        for (; t + 4 <= lim; t += 4) {
            int s0 = __shfl_sync(0xffffffffu, myidx, t);
            int s1 = __shfl_sync(0xffffffffu, myidx, t + 1);
            int s2 = __shfl_sync(0xffffffffu, myidx, t + 2);
            int s3 = __shfl_sync(0xffffffffu, myidx, t + 3);
            float d0 = __ldg(g_dg + s0);
            float d1 = __ldg(g_dg + s1);
            float d2 = __ldg(g_dg + s2);
            float d3 = __ldg(g_dg + s3);
            uint2 v0 = __ldg(hh2 + (size_t)s0 * 32 + lane);
            uint2 v1 = __ldg(hh2 + (size_t)s1 * 32 + lane);
            uint2 v2 = __ldg(hh2 + (size_t)s2 * 32 + lane);
            uint2 v3 = __ldg(hh2 + (size_t)s3 * 32 + lane);
            a0 = fmaf(d0, bf_lo(v0.x), a0); a1 = fmaf(d0, bf_hi(v0.x), a1);
            a2 = fmaf(d0, bf_lo(v0.y), a2); a3 = fmaf(d0, bf_hi(v0.y), a3);
            a0 = fmaf(d1, bf_lo(v1.x), a0); a1 = fmaf(d1, bf_hi(v1.x), a1);
            a2 = fmaf(d1, bf_lo(v1.y), a2); a3 = fmaf(d1, bf_hi(v1.y), a3);
            a0 = fmaf(d2, bf_lo(v2.x), a0); a1 = fmaf(d2, bf_hi(v2.x), a1);
            a2 = fmaf(d2, bf_lo(v2.y), a2); a3 = fmaf(d2, bf_hi(v2.y), a3);
            a0 = fmaf(d3, bf_lo(v3.x), a0); a1 = fmaf(d3, bf_hi(v3.x), a1);
            a2 = fmaf(d3, bf_lo(v3.y), a2); a3 = fmaf(d3, bf_hi(v3.y), a3);
        }
        for (; t < lim; t++) {
            int s = __shfl_sync(0xffffffffu, myidx, t);
            float ds = __ldg(g_dg + s);
            uint2 v = __ldg(hh2 + (size_t)s * 32 + lane);
            a0 = fmaf(ds, bf_lo(v.x), a0);
            a1 = fmaf(ds, bf_hi(v.x), a1);
            a2 = fmaf(ds, bf_lo(v.y), a2);
            a3 = fmaf(ds, bf_hi(v.y), a3);
        }
    }

    float4 gb = ((const float4*)gcn_b)[lane];
    float4 fa = ((const float4*)g_fa)[lane];
    float sum = fmaxf(dgi * a0 + gb.x, 0.0f) * fa.x
              + fmaxf(dgi * a1 + gb.y, 0.0f) * fa.y
              + fmaxf(dgi * a2 + gb.z, 0.0f) * fa.z
              + fmaxf(dgi * a3 + gb.w, 0.0f) * fa.w;
#pragma unroll
    for (int o = 16; o > 0; o >>= 1) sum += __shfl_down_sync(0xffffffffu, sum, o);
    if (lane == 0) out[node] = sum + g_fc;
}

// ============================================================================
// launch. gemm_fused stays the 4th launched kernel for ncu capture.
// ============================================================================
extern "C" void kernel_launch(void* const* d_in, const int* in_sizes, int n_in,
                              void* d_out, int out_size)
{
    const float* x        = (const float*)d_in[0];
    const int*   ei       = (const int*)  d_in[1];
    const float* W_x      = (const float*)d_in[3];
    const float* w_c      = (const float*)d_in[4];
    const float* b        = (const float*)d_in[5];
    const float* theta_b  = (const float*)d_in[7];
    const float* gcn_w    = (const float*)d_in[8];
    const float* gcn_b    = (const float*)d_in[9];
    const float* bn_gamma = (const float*)d_in[10];
    const float* bn_beta  = (const float*)d_in[11];
    const float* bn_mean  = (const float*)d_in[12];
    const float* bn_var   = (const float*)d_in[13];
    const float* lin_w    = (const float*)d_in[14];
    const float* lin_b    = (const float*)d_in[15];
    float* out = (float*)d_out;

    const int* src = ei;
    const int* dst = ei + N_EDGES;

    const int SMF = SMU * 4;  // 141312 B

    static cudaStream_t s1 = nullptr;
    static cudaEvent_t evRoot, evCsr;
    if (!s1) {
        cudaStreamCreateWithFlags(&s1, cudaStreamNonBlocking);
        cudaEventCreateWithFlags(&evRoot, cudaEventDisableTiming);
        cudaEventCreateWithFlags(&evCsr,  cudaEventDisableTiming);
        cudaFuncSetAttribute((const void*)gemm_fused,
                             cudaFuncAttributeMaxDynamicSharedMemorySize, SMF);
    }

    uint32_t *hhp, *wcp;
    cudaGetSymbolAddress((void**)&hhp, g_hhb);
    cudaGetSymbolAddress((void**)&wcp, g_Wc);

    // fork s1 from main at graph root
    cudaEventRecord(evRoot, 0);
    cudaStreamWaitEvent(s1, evRoot, 0);

    prep_all<<<257, 256>>>(W_x, gcn_w, theta_b, b, w_c,                 // #1 (main)
                           bn_gamma, bn_beta, bn_mean, bn_var, lin_w, lin_b);
    count_kernel<<<(N_EDGES + 255) / 256, 256, 0, s1>>>(dst);           // #2 (s1)
    scan_a<<<NB, 256, 0, s1>>>();                                       // #3 (s1)
    gemm_fused<<<(N_NODES + 127) / 128, 512, SMF>>>(x, wcp, hhp, N_NODES); // #4 (main)
    scan_bc<<<NB, 256, 0, s1>>>();                                      // #5 (s1)
    fill_kernel<<<(N_EDGES + 255) / 256, 256, 0, s1>>>(src, dst);       // #6 (s1)
    cudaEventRecord(evCsr, s1);

    // join: gather needs gemm (stream order) + CSR (event)
    cudaStreamWaitEvent(0, evCsr, 0);
    gather_finalize<<<(N_NODES * 32 + 255) / 256, 256>>>(gcn_b, out);   // #7 (main)
}

// round 12
// speedup vs baseline: 1.2108x; 1.2108x over previous
#include <cuda_runtime.h>
#include <cstdint>
#include <math.h>

#define N_NODES 50000
#define N_EDGES 640000
#define NH (N_NODES * 128)
#define NB 196  // ceil(N_NODES / 256)

// ---------------- scratch (static device globals) ---------------------------
// INVARIANT: g_indeg and g_cursor are zero at the start of every kernel_launch
// call: zero-initialized at module load; scan_bc re-zeros g_indeg after
// consuming it and zeroes g_cursor before fill uses it, every run.
__device__ uint32_t g_hhb[NH / 2];    // Hs @ gcn_w (unscaled), bf16x2 packed
__device__ uint32_t g_Wc[4 * 8192];   // f16x2 k-pair packed weights: i, c, o, gcn_w
__device__ int   g_indeg[N_NODES];
__device__ float g_dg[N_NODES];       // rsqrt(1 + indeg)
__device__ int   g_off[N_NODES + 1];
__device__ int   g_cursor[N_NODES];
__device__ int   g_csr[N_EDGES];
__device__ int   g_part[256];
// fused per-channel constants
__device__ float g_cb0[128], g_cb1[128], g_cb2[128], g_wc2[128];
__device__ float g_fa[128];
__device__ float g_fc;

// ---------------- helpers ----------------------------------------------------
__device__ __forceinline__ float tanhfast(float x) {
    float r; asm("tanh.approx.f32 %0, %1;" : "=f"(r) : "f"(x)); return r;
}
__device__ __forceinline__ float sigfast(float x) {
    return 0.5f * tanhfast(0.5f * x) + 0.5f;
}
__device__ __forceinline__ uint32_t pack_bf16x2(float hi, float lo) {
    uint32_t u; asm("cvt.rn.bf16x2.f32 %0, %1, %2;" : "=r"(u) : "f"(hi), "f"(lo)); return u;
}
__device__ __forceinline__ uint32_t pack_f16x2(float hi, float lo) {
    uint32_t u; asm("cvt.rn.f16x2.f32 %0, %1, %2;" : "=r"(u) : "f"(hi), "f"(lo)); return u;
}
__device__ __forceinline__ float bf_lo(uint32_t u) { return __uint_as_float(u << 16); }
__device__ __forceinline__ float bf_hi(uint32_t u) { return __uint_as_float(u & 0xffff0000u); }
// f16 MMA: D(f32) += A(f16) * B(f16), m16n8k16, row.col
__device__ __forceinline__ void mma_f16(float* d, const uint32_t* a, uint32_t b0, uint32_t b1) {
    asm volatile(
        "mma.sync.aligned.m16n8k16.row.col.f32.f16.f16.f32 "
        "{%0,%1,%2,%3}, {%4,%5,%6,%7}, {%8,%9}, {%0,%1,%2,%3};"
        : "+f"(d[0]), "+f"(d[1]), "+f"(d[2]), "+f"(d[3])
        : "r"(a[0]), "r"(a[1]), "r"(a[2]), "r"(a[3]), "r"(b0), "r"(b1));
}
__device__ __forceinline__ uint32_t smem_u32(const void* p) {
    uint32_t a;
    asm("{ .reg .u64 t; cvta.to.shared.u64 t, %1; cvt.u32.u64 %0, t; }" : "=r"(a) : "l"(p));
    return a;
}
__device__ __forceinline__ void cp_async16(uint32_t daddr, const void* saddr, int srcsz) {
    asm volatile("cp.async.cg.shared.global [%0], [%1], 16, %2;"
                 :: "r"(daddr), "l"(saddr), "r"(srcsz) : "memory");
}

// ---------------- prep: weights->f16x2 k-pairs + per-channel constants -------
// g_Wc matrix m (i,c,o,gcn): [k2][n] u32 = {W[2k2][n] lo, W[2k2+1][n] hi}
__global__ void prep_all(const float* __restrict__ Wx, const float* __restrict__ gcn,
                         const float* __restrict__ theta_b, const float* __restrict__ b,
                         const float* __restrict__ w_c,
                         const float* __restrict__ gamma, const float* __restrict__ beta,
                         const float* __restrict__ mean, const float* __restrict__ var,
                         const float* __restrict__ lin_w, const float* __restrict__ lin_b) {
    if (blockIdx.x < 128) {
        int i = blockIdx.x * 256 + threadIdx.x;   // 0..32767
        int m = i >> 13, rem = i & 8191;
        int k2 = rem >> 7, n = rem & 127;
        const float* S = (m == 0) ? Wx
                       : (m == 1) ? Wx + 2 * 16384
                       : (m == 2) ? Wx + 3 * 16384 : gcn;
        g_Wc[i] = pack_f16x2(S[(2 * k2 + 1) * 128 + n], S[2 * k2 * 128 + n]);
        return;
    }
    int ch = threadIdx.x;
    if (ch >= 128) return;
    g_cb0[ch] = theta_b[ch] + b[ch];
    g_cb1[ch] = theta_b[256 + ch] + b[256 + ch];
    g_cb2[ch] = theta_b[384 + ch] + b[384 + ch];
    g_wc2[ch] = w_c[256 + ch];
    float sc = gamma[ch] * rsqrtf(var[ch] + 1e-5f);
    g_fa[ch] = sc * lin_w[ch];
    __shared__ float red[128];
    red[ch] = (beta[ch] - mean[ch] * sc) * lin_w[ch];
    __syncthreads();
    for (int o = 64; o > 0; o >>= 1) { if (ch < o) red[ch] += red[ch + o]; __syncthreads(); }
    if (ch == 0) g_fc = red[0] + lin_b[0];
}

__global__ void count_kernel(const int* __restrict__ dst) {
    int e = blockIdx.x * blockDim.x + threadIdx.x;
    if (e < N_EDGES) atomicAdd(&g_indeg[dst[e]], 1);
}

// ---- scan stage A ----
__global__ __launch_bounds__(256) void scan_a() {
    int i = blockIdx.x * 256 + threadIdx.x;
    int v = (i < N_NODES) ? g_indeg[i] : 0;
    int lane = threadIdx.x & 31, warp = threadIdx.x >> 5;
#pragma unroll
    for (int o = 16; o > 0; o >>= 1) v += __shfl_down_sync(0xffffffffu, v, o);
    __shared__ int ws[8];
    if (lane == 0) ws[warp] = v;
    __syncthreads();
    if (threadIdx.x == 0) {
        int s = 0;
#pragma unroll
        for (int w = 0; w < 8; w++) s += ws[w];
        g_part[blockIdx.x] = s;
    }
}
// ---- scan stage BC ----
__global__ __launch_bounds__(256) void scan_bc() {
    int t = threadIdx.x, lane = t & 31, warp = t >> 5;
    __shared__ int s2[256];
    __shared__ int ws[8];
    {
        int v = (t < NB) ? g_part[t] : 0;
        int x = v;
#pragma unroll
        for (int o = 1; o < 32; o <<= 1) {
            int y = __shfl_up_sync(0xffffffffu, x, o);
            if (lane >= o) x += y;
        }
        if (lane == 31) ws[warp] = x;
        __syncthreads();
        if (warp == 0 && lane < 8) {
            int w = ws[lane];
#pragma unroll
            for (int o = 1; o < 8; o <<= 1) {
                int y = __shfl_up_sync(0xffu, w, o);
                if (lane >= o) w += y;
            }
            ws[lane] = w;
        }
        __syncthreads();
        s2[t] = x + (warp > 0 ? ws[warp - 1] : 0);
        __syncthreads();
    }
    int blockbase = (blockIdx.x == 0) ? 0 : s2[blockIdx.x - 1];
    __syncthreads();
    int i = blockIdx.x * 256 + t;
    int v = (i < N_NODES) ? g_indeg[i] : 0;
    int x = v;
#pragma unroll
    for (int o = 1; o < 32; o <<= 1) {
        int y = __shfl_up_sync(0xffffffffu, x, o);
        if (lane >= o) x += y;
    }
    if (lane == 31) ws[warp] = x;
    __syncthreads();
    if (warp == 0 && lane < 8) {
        int w = ws[lane];
#pragma unroll
        for (int o = 1; o < 8; o <<= 1) {
            int y = __shfl_up_sync(0xffu, w, o);
            if (lane >= o) w += y;
        }
        ws[lane] = w;
    }
    __syncthreads();
    if (i < N_NODES) {
        g_off[i] = x - v + (warp > 0 ? ws[warp - 1] : 0) + blockbase;
        g_dg[i] = rsqrtf(1.0f + (float)v);
        g_cursor[i] = 0;
        g_indeg[i] = 0;  // restore invariant for next replay
    }
    if (blockIdx.x == 0 && t == 0) g_off[N_NODES] = N_EDGES;
}

__global__ void fill_kernel(const int* __restrict__ src, const int* __restrict__ dst) {
    int e = blockIdx.x * blockDim.x + threadIdx.x;
    if (e >= N_EDGES) return;
    int d = dst[e];
    g_csr[g_off[d] + atomicAdd(&g_cursor[d], 1)] = src[e];
}

// ============================================================================
// Fully fused f16-MMA GEMM: gates + LSTM -> Hs(f16 smem) -> Hs@gcn_w -> bf16 hh.
// 512 threads, 16 warps (4m x 4n), warp tile 32x32, m16n8k16.
// ALL B loads issued up front (2 commit groups); A via LDG+cvt overlaps them.
// smem u32 map: A0=0 (4608, pitch36)  A1=4608  | Hs chunks reuse A0/A1
//               B0g=9216+g*4352 (x3)  B1g=22272+g*4352 (x3)
//               G0=35328 G1=39680 (gcn_w, pitch136)
//               SMC=44032 (512 epilogue constants)   total 44544 u32 = 178KB
// ============================================================================
#define A0O 0
#define A1O 4608
#define B0O 9216
#define B1O 22272
#define G0O 35328
#define G1O 39680
#define SMC 44032
#define SMU 44544

__global__ __launch_bounds__(512, 1) void gemm_fused(
    const float* __restrict__ A, const uint32_t* __restrict__ W,
    uint32_t* __restrict__ out, int M)
{
    extern __shared__ uint32_t sm[];
    const int tid = threadIdx.x, lane = tid & 31;
    const int wid = tid >> 5, wm = wid >> 2, wn = wid & 3;
    const int q = lane >> 2, r = lane & 3;
    const int rowblk = blockIdx.x * 128;
    const uint32_t sbase = smem_u32(sm);

    // ---- group 1: B chunk0 (3 gates x 32 k2-rows x 128 u32 = 3072 f4) ----
#pragma unroll
    for (int t = 0; t < 6; t++) {
        int i = tid + t * 512;
        int g = i >> 10, rj = i & 1023;
        int row = rj >> 5, j = rj & 31;
        cp_async16(sbase + (B0O + g * 4352 + row * 136 + j * 4) * 4,
                   W + g * 8192 + row * 128 + j * 4, 16);
    }
    asm volatile("cp.async.commit_group;" ::: "memory");
    // ---- group 2: B chunk1 (3072 f4) + gcn_w both chunks (2048 f4) ----
#pragma unroll
    for (int t = 0; t < 10; t++) {
        int i = tid + t * 512;
        if (i < 3072) {
            int g = i >> 10, rj = i & 1023;
            int row = rj >> 5, j = rj & 31;
            cp_async16(sbase + (B1O + g * 4352 + row * 136 + j * 4) * 4,
                       W + g * 8192 + (32 + row) * 128 + j * 4, 16);
        } else {
            int k = i - 3072;               // 0..2047
            int row = k >> 5, j = k & 31;   // row 0..63
            int gc = row >> 5;
            cp_async16(sbase + ((gc ? G1O : G0O) + (row & 31) * 136 + j * 4) * 4,
                       W + 3 * 8192 + row * 128 + j * 4, 16);
        }
    }
    asm volatile("cp.async.commit_group;" ::: "memory");

    // ---- stage epilogue constants ----
    {
        int a = tid >> 7, c = tid & 127;
        float v = (a == 0) ? g_cb0[c] : (a == 1) ? g_cb1[c]
                : (a == 2) ? g_cb2[c] : g_wc2[c];
        sm[SMC + tid] = __float_as_uint(v);
    }

    // ---- A: LDG f32 -> f16x2 STS, both chunks (4096 f4, 8/thread) ----
#pragma unroll
    for (int t = 0; t < 8; t++) {
        int i = tid + t * 512;
        int row = i >> 5, jj = i & 31;
        int chunk = jj >> 4, j = jj & 15;
        int gr = rowblk + row;
        float4 v = make_float4(0.f, 0.f, 0.f, 0.f);
        if (gr < M) v = *(const float4*)(A + (size_t)gr * 128 + chunk * 64 + j * 4);
        uint2 u;
        u.x = pack_f16x2(v.y, v.x);
        u.y = pack_f16x2(v.w, v.z);
        *(uint2*)(&sm[(chunk ? A1O : A0O) + row * 36 + j * 2]) = u;
    }

    float C[3][2][4][4];
#pragma unroll
    for (int g = 0; g < 3; g++)
#pragma unroll
        for (int i = 0; i < 2; i++)
#pragma unroll
            for (int j = 0; j < 4; j++)
#pragma unroll
                for (int k = 0; k < 4; k++) C[g][i][j][k] = 0.0f;

    // ================= phase 1 =================
#pragma unroll
    for (int chunk = 0; chunk < 2; chunk++) {
        if (chunk == 0)
            asm volatile("cp.async.wait_group 1;" ::: "memory");
        else
            asm volatile("cp.async.wait_group 0;" ::: "memory");
        __syncthreads();
        const uint32_t* Ac = sm + (chunk ? A1O : A0O);
        const int bbase = chunk ? B1O : B0O;
#pragma unroll
        for (int ks = 0; ks < 4; ks++) {
            const int kb2 = ks * 8;
            uint32_t a[2][4];
#pragma unroll
            for (int ma = 0; ma < 2; ma++) {
                int m = wm * 32 + ma * 16 + q;
                const uint32_t* ap = &Ac[m * 36 + kb2 + r];
                a[ma][0] = ap[0];
                a[ma][1] = ap[8 * 36];
                a[ma][2] = ap[4];
                a[ma][3] = ap[8 * 36 + 4];
            }
#pragma unroll
            for (int g = 0; g < 3; g++) {
                const uint32_t* bs = sm + bbase + g * 4352;
#pragma unroll
                for (int na = 0; na < 4; na++) {
                    int n = wn * 32 + na * 8 + q;
                    const uint32_t* bp = &bs[(kb2 + r) * 136 + n];
                    uint32_t b0 = bp[0], b1 = bp[4 * 136];
#pragma unroll
                    for (int ma = 0; ma < 2; ma++) mma_f16(C[g][ma][na], a[ma], b0, b1);
                }
            }
        }
        if (chunk == 0) __syncthreads();  // everyone done before next chunk reads
    }
    __syncthreads();  // all phase-1 reads of A0/A1 done before Hs overwrite

    // ============ LSTM epilogue -> Hs (f16x2) into A0/A1 regions ============
#pragma unroll
    for (int ma = 0; ma < 2; ma++) {
#pragma unroll
        for (int half = 0; half < 2; half++) {
            int lrow = wm * 32 + ma * 16 + q + half * 8;
#pragma unroll
            for (int na = 0; na < 4; na++) {
                int ch = wn * 32 + na * 8 + 2 * r;
                float hlo, hhi;
                {
                    float zi = C[0][ma][na][half * 2] + __uint_as_float(sm[SMC + ch]);
                    float zc = C[1][ma][na][half * 2] + __uint_as_float(sm[SMC + 128 + ch]);
                    float zo = C[2][ma][na][half * 2] + __uint_as_float(sm[SMC + 256 + ch]);
                    float I = sigfast(zi);
                    float T = tanhfast(zc);
                    float Cs = I * T;
                    float O = sigfast(zo + __uint_as_float(sm[SMC + 384 + ch]) * Cs);
                    hlo = O * tanhfast(Cs);
                }
                {
                    float zi = C[0][ma][na][half * 2 + 1] + __uint_as_float(sm[SMC + ch + 1]);
                    float zc = C[1][ma][na][half * 2 + 1] + __uint_as_float(sm[SMC + 129 + ch]);
                    float zo = C[2][ma][na][half * 2 + 1] + __uint_as_float(sm[SMC + 257 + ch]);
                    float I = sigfast(zi);
                    float T = tanhfast(zc);
                    float Cs = I * T;
                    float O = sigfast(zo + __uint_as_float(sm[SMC + 385 + ch]) * Cs);
                    hhi = O * tanhfast(Cs);
                }
                int cchunk = ch >> 6;
                int col = ((wn & 1) << 4) + na * 4 + r;
                sm[(cchunk ? A1O : A0O) + lrow * 36 + col] = pack_f16x2(hhi, hlo);
            }
        }
    }
    __syncthreads();

    // ================= phase 2: hh = Hs @ gcn_w =============================
    float D[2][4][4];
#pragma unroll
    for (int i = 0; i < 2; i++)
#pragma unroll
        for (int j = 0; j < 4; j++)
#pragma unroll
            for (int k = 0; k < 4; k++) D[i][j][k] = 0.0f;

#pragma unroll
    for (int chunk = 0; chunk < 2; chunk++) {
        const uint32_t* as = sm + (chunk ? A1O : A0O);
        const uint32_t* bs = sm + (chunk ? G1O : G0O);
#pragma unroll
        for (int ks = 0; ks < 4; ks++) {
            const int kb2 = ks * 8;
            uint32_t a[2][4];
#pragma unroll
            for (int ma = 0; ma < 2; ma++) {
                int m = wm * 32 + ma * 16 + q;
                const uint32_t* ap = &as[m * 36 + kb2 + r];
                a[ma][0] = ap[0];
                a[ma][1] = ap[8 * 36];
                a[ma][2] = ap[4];
                a[ma][3] = ap[8 * 36 + 4];
            }
#pragma unroll
            for (int na = 0; na < 4; na++) {
                int n = wn * 32 + na * 8 + q;
                const uint32_t* bp = &bs[(kb2 + r) * 136 + n];
                uint32_t b0 = bp[0], b1 = bp[4 * 136];
#pragma unroll
                for (int ma = 0; ma < 2; ma++) mma_f16(D[ma][na], a[ma], b0, b1);
            }
        }
    }

    // ---- epilogue 2: write hh as bf16x2 ----
#pragma unroll
    for (int ma = 0; ma < 2; ma++) {
#pragma unroll
        for (int half = 0; half < 2; half++) {
            int row = rowblk + wm * 32 + ma * 16 + q + half * 8;
            if (row >= M) continue;
#pragma unroll
            for (int na = 0; na < 4; na++) {
                int ch = wn * 32 + na * 8 + 2 * r;
                out[(size_t)row * 64 + (ch >> 1)] =
                    pack_bf16x2(D[ma][na][half * 2 + 1], D[ma][na][half * 2]);
            }
        }
    }
}

// ============================================================================
// gather + finalize: warp per node, bf16 hh; cnt from CSR offsets
// ============================================================================
__global__ __launch_bounds__(256) void gather_finalize(const float* __restrict__ gcn_b,
                                                       float* __restrict__ out)
{
    int node = (blockIdx.x * blockDim.x + threadIdx.x) >> 5;
    int lane = threadIdx.x & 31;
    if (node >= N_NODES) return;
    int base = g_off[node];
    int cnt = g_off[node + 1] - base;
    float dgi = g_dg[node];

    const uint2* hh2 = (const uint2*)g_hhb;
    uint2 hv = hh2[(size_t)node * 32 + lane];
    float a0 = dgi * bf_lo(hv.x), a1 = dgi * bf_hi(hv.x);
    float a2 = dgi * bf_lo(hv.y), a3 = dgi * bf_hi(hv.y);

    for (int e0 = 0; e0 < cnt; e0 += 32) {
        int myidx = (e0 + lane < cnt) ? g_csr[base + e0 + lane] : 0;
        int lim = min(32, cnt - e0);
        int t = 0;
        for (; t + 4 <= lim; t += 4) {
            int s0 = __shfl_sync(0xffffffffu, myidx, t);
            int s1 = __shfl_sync(0xffffffffu, myidx, t + 1);
            int s2 = __shfl_sync(0xffffffffu, myidx, t + 2);
            int s3 = __shfl_sync(0xffffffffu, myidx, t + 3);
            float d0 = __ldg(g_dg + s0);
            float d1 = __ldg(g_dg + s1);
            float d2 = __ldg(g_dg + s2);
            float d3 = __ldg(g_dg + s3);
            uint2 v0 = __ldg(hh2 + (size_t)s0 * 32 + lane);
            uint2 v1 = __ldg(hh2 + (size_t)s1 * 32 + lane);
            uint2 v2 = __ldg(hh2 + (size_t)s2 * 32 + lane);
            uint2 v3 = __ldg(hh2 + (size_t)s3 * 32 + lane);
            a0 = fmaf(d0, bf_lo(v0.x), a0); a1 = fmaf(d0, bf_hi(v0.x), a1);
            a2 = fmaf(d0, bf_lo(v0.y), a2); a3 = fmaf(d0, bf_hi(v0.y), a3);
            a0 = fmaf(d1, bf_lo(v1.x), a0); a1 = fmaf(d1, bf_hi(v1.x), a1);
            a2 = fmaf(d1, bf_lo(v1.y), a2); a3 = fmaf(d1, bf_hi(v1.y), a3);
            a0 = fmaf(d2, bf_lo(v2.x), a0); a1 = fmaf(d2, bf_hi(v2.x), a1);
            a2 = fmaf(d2, bf_lo(v2.y), a2); a3 = fmaf(d2, bf_hi(v2.y), a3);
            a0 = fmaf(d3, bf_lo(v3.x), a0); a1 = fmaf(d3, bf_hi(v3.x), a1);
            a2 = fmaf(d3, bf_lo(v3.y), a2); a3 = fmaf(d3, bf_hi(v3.y), a3);
        }
        for (; t < lim; t++) {
            int s = __shfl_sync(0xffffffffu, myidx, t);
            float ds = __ldg(g_dg + s);
            uint2 v = __ldg(hh2 + (size_t)s * 32 + lane);
            a0 = fmaf(ds, bf_lo(v.x), a0);
            a1 = fmaf(ds, bf_hi(v.x), a1);
            a2 = fmaf(ds, bf_lo(v.y), a2);
            a3 = fmaf(ds, bf_hi(v.y), a3);
        }
    }

    float4 gb = ((const float4*)gcn_b)[lane];
    float4 fa = ((const float4*)g_fa)[lane];
    float sum = fmaxf(dgi * a0 + gb.x, 0.0f) * fa.x
              + fmaxf(dgi * a1 + gb.y, 0.0f) * fa.y
              + fmaxf(dgi * a2 + gb.z, 0.0f) * fa.z
              + fmaxf(dgi * a3 + gb.w, 0.0f) * fa.w;
#pragma unroll
    for (int o = 16; o > 0; o >>= 1) sum += __shfl_down_sync(0xffffffffu, sum, o);
    if (lane == 0) out[node] = sum + g_fc;
}

// ============================================================================
// launch. gemm_fused stays the 4th launched kernel for ncu capture.
// ============================================================================
extern "C" void kernel_launch(void* const* d_in, const int* in_sizes, int n_in,
                              void* d_out, int out_size)
{
    const float* x        = (const float*)d_in[0];
    const int*   ei       = (const int*)  d_in[1];
    const float* W_x      = (const float*)d_in[3];
    const float* w_c      = (const float*)d_in[4];
    const float* b        = (const float*)d_in[5];
    const float* theta_b  = (const float*)d_in[7];
    const float* gcn_w    = (const float*)d_in[8];
    const float* gcn_b    = (const float*)d_in[9];
    const float* bn_gamma = (const float*)d_in[10];
    const float* bn_beta  = (const float*)d_in[11];
    const float* bn_mean  = (const float*)d_in[12];
    const float* bn_var   = (const float*)d_in[13];
    const float* lin_w    = (const float*)d_in[14];
    const float* lin_b    = (const float*)d_in[15];
    float* out = (float*)d_out;

    const int* src = ei;
    const int* dst = ei + N_EDGES;

    const int SMF = SMU * 4;  // 178176 B

    static cudaStream_t s1 = nullptr;
    static cudaEvent_t evRoot, evCsr;
    if (!s1) {
        cudaStreamCreateWithFlags(&s1, cudaStreamNonBlocking);
        cudaEventCreateWithFlags(&evRoot, cudaEventDisableTiming);
        cudaEventCreateWithFlags(&evCsr,  cudaEventDisableTiming);
        cudaFuncSetAttribute((const void*)gemm_fused,
                             cudaFuncAttributeMaxDynamicSharedMemorySize, SMF);
    }

    uint32_t *hhp, *wcp;
    cudaGetSymbolAddress((void**)&hhp, g_hhb);
    cudaGetSymbolAddress((void**)&wcp, g_Wc);

    // fork s1 from main at graph root
    cudaEventRecord(evRoot, 0);
    cudaStreamWaitEvent(s1, evRoot, 0);

    prep_all<<<129, 256>>>(W_x, gcn_w, theta_b, b, w_c,                 // #1 (main)
                           bn_gamma, bn_beta, bn_mean, bn_var, lin_w, lin_b);
    count_kernel<<<(N_EDGES + 255) / 256, 256, 0, s1>>>(dst);           // #2 (s1)
    scan_a<<<NB, 256, 0, s1>>>();                                       // #3 (s1)
    gemm_fused<<<(N_NODES + 127) / 128, 512, SMF>>>(x, wcp, hhp, N_NODES); // #4 (main)
    scan_bc<<<NB, 256, 0, s1>>>();                                      // #5 (s1)
    fill_kernel<<<(N_EDGES + 255) / 256, 256, 0, s1>>>(src, dst);       // #6 (s1)
    cudaEventRecord(evCsr, s1);

    // join: gather needs gemm (stream order) + CSR (event)
    cudaStreamWaitEvent(0, evCsr, 0);
    gather_finalize<<<(N_NODES * 32 + 255) / 256, 256>>>(gcn_b, out);   // #7 (main)
}

// round 13
// speedup vs baseline: 1.2143x; 1.0029x over previous
#include <cuda_runtime.h>
#include <cstdint>
#include <math.h>

#define N_NODES 50000
#define N_EDGES 640000
#define NH (N_NODES * 128)
#define NB 196  // ceil(N_NODES / 256)

// ---------------- scratch (static device globals) ---------------------------
// INVARIANT: g_indeg and g_cursor are zero at the start of every kernel_launch
// call: zero-initialized at module load; scan_bc re-zeros g_indeg after
// consuming it and zeroes g_cursor before fill uses it, every run.
__device__ uint32_t g_hhb[NH / 2];    // Hs @ gcn_w (unscaled), bf16x2 packed
// f16x2 weights pre-arranged as the smem fragment image:
// per matrix (i,c,o,gcn): [chunk c][ks][n][r][slot] -> off = c*4096 + ks*1024 + n*8 + r*2 + slot
// where k2 = c*32 + ks*8 + slot*4 + r, u32 = {W[2k2][n] lo, W[2k2+1][n] hi}
__device__ uint32_t g_Wc[4 * 8192];
__device__ int   g_indeg[N_NODES];
__device__ float g_dg[N_NODES];       // rsqrt(1 + indeg)
__device__ int   g_off[N_NODES + 1];
__device__ int   g_cursor[N_NODES];
__device__ int   g_csr[N_EDGES];
__device__ int   g_part[256];
// fused per-channel constants
__device__ float g_cb0[128], g_cb1[128], g_cb2[128], g_wc2[128];
__device__ float g_fa[128];
__device__ float g_fc;

// ---------------- helpers ----------------------------------------------------
__device__ __forceinline__ float tanhfast(float x) {
    float r; asm("tanh.approx.f32 %0, %1;" : "=f"(r) : "f"(x)); return r;
}
__device__ __forceinline__ float sigfast(float x) {
    return 0.5f * tanhfast(0.5f * x) + 0.5f;
}
__device__ __forceinline__ uint32_t pack_bf16x2(float hi, float lo) {
    uint32_t u; asm("cvt.rn.bf16x2.f32 %0, %1, %2;" : "=r"(u) : "f"(hi), "f"(lo)); return u;
}
__device__ __forceinline__ uint32_t pack_f16x2(float hi, float lo) {
    uint32_t u; asm("cvt.rn.f16x2.f32 %0, %1, %2;" : "=r"(u) : "f"(hi), "f"(lo)); return u;
}
__device__ __forceinline__ float bf_lo(uint32_t u) { return __uint_as_float(u << 16); }
__device__ __forceinline__ float bf_hi(uint32_t u) { return __uint_as_float(u & 0xffff0000u); }
__device__ __forceinline__ void mma_f16(float* d, const uint32_t* a, uint32_t b0, uint32_t b1) {
    asm volatile(
        "mma.sync.aligned.m16n8k16.row.col.f32.f16.f16.f32 "
        "{%0,%1,%2,%3}, {%4,%5,%6,%7}, {%8,%9}, {%0,%1,%2,%3};"
        : "+f"(d[0]), "+f"(d[1]), "+f"(d[2]), "+f"(d[3])
        : "r"(a[0]), "r"(a[1]), "r"(a[2]), "r"(a[3]), "r"(b0), "r"(b1));
}
__device__ __forceinline__ uint32_t smem_u32(const void* p) {
    uint32_t a;
    asm("{ .reg .u64 t; cvta.to.shared.u64 t, %1; cvt.u32.u64 %0, t; }" : "=r"(a) : "l"(p));
    return a;
}
__device__ __forceinline__ void cp_async16(uint32_t daddr, const void* saddr, int srcsz) {
    asm volatile("cp.async.cg.shared.global [%0], [%1], 16, %2;"
                 :: "r"(daddr), "l"(saddr), "r"(srcsz) : "memory");
}

// ---------------- prep: weights -> fragment-image f16x2 + constants ----------
__global__ void prep_all(const float* __restrict__ Wx, const float* __restrict__ gcn,
                         const float* __restrict__ theta_b, const float* __restrict__ b,
                         const float* __restrict__ w_c,
                         const float* __restrict__ gamma, const float* __restrict__ beta,
                         const float* __restrict__ mean, const float* __restrict__ var,
                         const float* __restrict__ lin_w, const float* __restrict__ lin_b) {
    if (blockIdx.x < 128) {
        int i = blockIdx.x * 256 + threadIdx.x;   // 0..32767
        int m = i >> 13, rem = i & 8191;
        int c = rem >> 12;
        int rem2 = rem & 4095;
        int ks = rem2 >> 10;
        int t = rem2 & 1023;
        int n = t >> 3;
        int u = t & 7;
        int rr = u >> 1, slot = u & 1;
        int k2 = c * 32 + ks * 8 + slot * 4 + rr;
        const float* S = (m == 0) ? Wx
                       : (m == 1) ? Wx + 2 * 16384
                       : (m == 2) ? Wx + 3 * 16384 : gcn;
        g_Wc[i] = pack_f16x2(S[(2 * k2 + 1) * 128 + n], S[2 * k2 * 128 + n]);
        return;
    }
    int ch = threadIdx.x;
    if (ch >= 128) return;
    g_cb0[ch] = theta_b[ch] + b[ch];
    g_cb1[ch] = theta_b[256 + ch] + b[256 + ch];
    g_cb2[ch] = theta_b[384 + ch] + b[384 + ch];
    g_wc2[ch] = w_c[256 + ch];
    float sc = gamma[ch] * rsqrtf(var[ch] + 1e-5f);
    g_fa[ch] = sc * lin_w[ch];
    __shared__ float red[128];
    red[ch] = (beta[ch] - mean[ch] * sc) * lin_w[ch];
    __syncthreads();
    for (int o = 64; o > 0; o >>= 1) { if (ch < o) red[ch] += red[ch + o]; __syncthreads(); }
    if (ch == 0) g_fc = red[0] + lin_b[0];
}

__global__ void count_kernel(const int* __restrict__ dst) {
    int e = blockIdx.x * blockDim.x + threadIdx.x;
    if (e < N_EDGES) atomicAdd(&g_indeg[dst[e]], 1);
}

// ---- scan stage A ----
__global__ __launch_bounds__(256) void scan_a() {
    int i = blockIdx.x * 256 + threadIdx.x;
    int v = (i < N_NODES) ? g_indeg[i] : 0;
    int lane = threadIdx.x & 31, warp = threadIdx.x >> 5;
#pragma unroll
    for (int o = 16; o > 0; o >>= 1) v += __shfl_down_sync(0xffffffffu, v, o);
    __shared__ int ws[8];
    if (lane == 0) ws[warp] = v;
    __syncthreads();
    if (threadIdx.x == 0) {
        int s = 0;
#pragma unroll
        for (int w = 0; w < 8; w++) s += ws[w];
        g_part[blockIdx.x] = s;
    }
}
// ---- scan stage BC ----
__global__ __launch_bounds__(256) void scan_bc() {
    int t = threadIdx.x, lane = t & 31, warp = t >> 5;
    __shared__ int s2[256];
    __shared__ int ws[8];
    {
        int v = (t < NB) ? g_part[t] : 0;
        int x = v;
#pragma unroll
        for (int o = 1; o < 32; o <<= 1) {
            int y = __shfl_up_sync(0xffffffffu, x, o);
            if (lane >= o) x += y;
        }
        if (lane == 31) ws[warp] = x;
        __syncthreads();
        if (warp == 0 && lane < 8) {
            int w = ws[lane];
#pragma unroll
            for (int o = 1; o < 8; o <<= 1) {
                int y = __shfl_up_sync(0xffu, w, o);
                if (lane >= o) w += y;
            }
            ws[lane] = w;
        }
        __syncthreads();
        s2[t] = x + (warp > 0 ? ws[warp - 1] : 0);
        __syncthreads();
    }
    int blockbase = (blockIdx.x == 0) ? 0 : s2[blockIdx.x - 1];
    __syncthreads();
    int i = blockIdx.x * 256 + t;
    int v = (i < N_NODES) ? g_indeg[i] : 0;
    int x = v;
#pragma unroll
    for (int o = 1; o < 32; o <<= 1) {
        int y = __shfl_up_sync(0xffffffffu, x, o);
        if (lane >= o) x += y;
    }
    if (lane == 31) ws[warp] = x;
    __syncthreads();
    if (warp == 0 && lane < 8) {
        int w = ws[lane];
#pragma unroll
        for (int o = 1; o < 8; o <<= 1) {
            int y = __shfl_up_sync(0xffu, w, o);
            if (lane >= o) w += y;
        }
        ws[lane] = w;
    }
    __syncthreads();
    if (i < N_NODES) {
        g_off[i] = x - v + (warp > 0 ? ws[warp - 1] : 0) + blockbase;
        g_dg[i] = rsqrtf(1.0f + (float)v);
        g_cursor[i] = 0;
        g_indeg[i] = 0;  // restore invariant for next replay
    }
    if (blockIdx.x == 0 && t == 0) g_off[N_NODES] = N_EDGES;
}

__global__ void fill_kernel(const int* __restrict__ src, const int* __restrict__ dst) {
    int e = blockIdx.x * blockDim.x + threadIdx.x;
    if (e >= N_EDGES) return;
    int d = dst[e];
    g_csr[g_off[d] + atomicAdd(&g_cursor[d], 1)] = src[e];
}

// ============================================================================
// Fused f16-MMA GEMM, 256 threads, M-tile 64, 8 warps (2m x 4n), tile 32x32.
// 2 CTAs/SM (regs capped 128). One B buffer sequenced B0 -> B1 -> gcn_w.
// Fragment-packed smem: every fragment pair is one LDS.64.
// smem u32: A0=0(2048) A1=2048(2048) B=4096(12288) SMC=16384(512) tot=16896
// ============================================================================
#define A0O 0
#define A1O 2048
#define BBO 4096
#define SMC 16384
#define SMU 16896

__global__ __launch_bounds__(256, 2) void gemm_fused(
    const float* __restrict__ A, const uint32_t* __restrict__ W,
    uint32_t* __restrict__ out, int M)
{
    extern __shared__ uint32_t sm[];
    const int tid = threadIdx.x, lane = tid & 31;
    const int wid = tid >> 5, wm = wid >> 2, wn = wid & 3;
    const int q = lane >> 2, r = lane & 3;
    const int rowblk = blockIdx.x * 64;
    const uint32_t sbase = smem_u32(sm);

    // ---- group: B chunk0 (3 gates x 4096 u32 = 3072 f4, 12/thread) ----
#pragma unroll
    for (int t = 0; t < 12; t++) {
        int i = tid + t * 256;
        int g = i >> 10, off4 = i & 1023;
        cp_async16(sbase + (BBO + g * 4096 + off4 * 4) * 4,
                   W + g * 8192 + off4 * 4, 16);
    }
    asm volatile("cp.async.commit_group;" ::: "memory");

    // ---- stage epilogue constants (512, 2/thread) ----
#pragma unroll
    for (int t = 0; t < 2; t++) {
        int idx = tid + t * 256;
        int a = idx >> 7, c = idx & 127;
        float v = (a == 0) ? g_cb0[c] : (a == 1) ? g_cb1[c]
                : (a == 2) ? g_cb2[c] : g_wc2[c];
        sm[SMC + idx] = __float_as_uint(v);
    }

    // ---- A: LDG f32 -> f16x2 fragment-image STS, both chunks (8 f4/thr) ----
#pragma unroll
    for (int t = 0; t < 8; t++) {
        int i = tid + t * 256;            // 0..2047
        int row = i >> 5, jj = i & 31;
        int chunk = jj >> 4, j = jj & 15;
        int gr = rowblk + row;
        float4 v = make_float4(0.f, 0.f, 0.f, 0.f);
        if (gr < M) v = *(const float4*)(A + (size_t)gr * 128 + chunk * 64 + j * 4);
        uint32_t base = chunk ? A1O : A0O;
        // k2 local = 2j and 2j+1
        int k2a = 2 * j, k2b = 2 * j + 1;
        int oa = base + (k2a >> 3) * 512 + row * 8 + (k2a & 3) * 2 + ((k2a >> 2) & 1);
        int ob = base + (k2b >> 3) * 512 + row * 8 + (k2b & 3) * 2 + ((k2b >> 2) & 1);
        sm[oa] = pack_f16x2(v.y, v.x);
        sm[ob] = pack_f16x2(v.w, v.z);
    }

    float C[3][2][4][4];
#pragma unroll
    for (int g = 0; g < 3; g++)
#pragma unroll
        for (int i = 0; i < 2; i++)
#pragma unroll
            for (int j = 0; j < 4; j++)
#pragma unroll
                for (int k = 0; k < 4; k++) C[g][i][j][k] = 0.0f;

    // ================= phase 1 =================
#pragma unroll
    for (int chunk = 0; chunk < 2; chunk++) {
        if (chunk == 1) {
            // B buffer free (sync below); stream in chunk1
#pragma unroll
            for (int t = 0; t < 12; t++) {
                int i = tid + t * 256;
                int g = i >> 10, off4 = i & 1023;
                cp_async16(sbase + (BBO + g * 4096 + off4 * 4) * 4,
                           W + g * 8192 + 4096 + off4 * 4, 16);
            }
            asm volatile("cp.async.commit_group;" ::: "memory");
        }
        asm volatile("cp.async.wait_group 0;" ::: "memory");
        __syncthreads();
        const uint32_t* Ac = sm + (chunk ? A1O : A0O);
#pragma unroll
        for (int ks = 0; ks < 4; ks++) {
            uint32_t a[2][4];
#pragma unroll
            for (int ma = 0; ma < 2; ma++) {
                int m = wm * 32 + ma * 16 + q;
                uint2 lo = *(const uint2*)&Ac[ks * 512 + m * 8 + r * 2];
                uint2 hi = *(const uint2*)&Ac[ks * 512 + (m + 8) * 8 + r * 2];
                a[ma][0] = lo.x; a[ma][2] = lo.y;
                a[ma][1] = hi.x; a[ma][3] = hi.y;
            }
#pragma unroll
            for (int g = 0; g < 3; g++) {
                const uint32_t* bs = sm + BBO + g * 4096;
#pragma unroll
                for (int na = 0; na < 4; na++) {
                    int n = wn * 32 + na * 8 + q;
                    uint2 b = *(const uint2*)&bs[ks * 1024 + n * 8 + r * 2];
#pragma unroll
                    for (int ma = 0; ma < 2; ma++) mma_f16(C[g][ma][na], a[ma], b.x, b.y);
                }
            }
        }
        __syncthreads();  // B buffer reads done (and, after chunk1, A reads done)
    }

    // ---- stream gcn_w (both chunks, 8192 u32 = 2048 f4) into B buffer ----
#pragma unroll
    for (int t = 0; t < 8; t++) {
        int i = tid + t * 256;
        cp_async16(sbase + (BBO + i * 4) * 4, W + 3 * 8192 + i * 4, 16);
    }
    asm volatile("cp.async.commit_group;" ::: "memory");

    // ============ LSTM epilogue -> Hs (f16x2 fragment-image) into A0/A1 =====
#pragma unroll
    for (int ma = 0; ma < 2; ma++) {
#pragma unroll
        for (int half = 0; half < 2; half++) {
            int lrow = wm * 32 + ma * 16 + q + half * 8;
#pragma unroll
            for (int na = 0; na < 4; na++) {
                int ch = wn * 32 + na * 8 + 2 * r;
                float hlo, hhi;
                {
                    float zi = C[0][ma][na][half * 2] + __uint_as_float(sm[SMC + ch]);
                    float zc = C[1][ma][na][half * 2] + __uint_as_float(sm[SMC + 128 + ch]);
                    float zo = C[2][ma][na][half * 2] + __uint_as_float(sm[SMC + 256 + ch]);
                    float I = sigfast(zi);
                    float T = tanhfast(zc);
                    float Cs = I * T;
                    float O = sigfast(zo + __uint_as_float(sm[SMC + 384 + ch]) * Cs);
                    hlo = O * tanhfast(Cs);
                }
                {
                    float zi = C[0][ma][na][half * 2 + 1] + __uint_as_float(sm[SMC + ch + 1]);
                    float zc = C[1][ma][na][half * 2 + 1] + __uint_as_float(sm[SMC + 129 + ch]);
                    float zo = C[2][ma][na][half * 2 + 1] + __uint_as_float(sm[SMC + 257 + ch]);
                    float I = sigfast(zi);
                    float T = tanhfast(zc);
                    float Cs = I * T;
                    float O = sigfast(zo + __uint_as_float(sm[SMC + 385 + ch]) * Cs);
                    hhi = O * tanhfast(Cs);
                }
                int k2 = ch >> 1;                 // 0..63
                int cchunk = k2 >> 5;
                int k2l = k2 & 31;
                int off = (cchunk ? A1O : A0O) + (k2l >> 3) * 512 + lrow * 8
                        + (k2l & 3) * 2 + ((k2l >> 2) & 1);
                sm[off] = pack_f16x2(hhi, hlo);
            }
        }
    }
    asm volatile("cp.async.wait_group 0;" ::: "memory");
    __syncthreads();

    // ================= phase 2: hh = Hs @ gcn_w =============================
    float D[2][4][4];
#pragma unroll
    for (int i = 0; i < 2; i++)
#pragma unroll
        for (int j = 0; j < 4; j++)
#pragma unroll
            for (int k = 0; k < 4; k++) D[i][j][k] = 0.0f;

#pragma unroll
    for (int chunk = 0; chunk < 2; chunk++) {
        const uint32_t* as = sm + (chunk ? A1O : A0O);
        const uint32_t* bs = sm + BBO + chunk * 4096;
#pragma unroll
        for (int ks = 0; ks < 4; ks++) {
            uint32_t a[2][4];
#pragma unroll
            for (int ma = 0; ma < 2; ma++) {
                int m = wm * 32 + ma * 16 + q;
                uint2 lo = *(const uint2*)&as[ks * 512 + m * 8 + r * 2];
                uint2 hi = *(const uint2*)&as[ks * 512 + (m + 8) * 8 + r * 2];
                a[ma][0] = lo.x; a[ma][2] = lo.y;
                a[ma][1] = hi.x; a[ma][3] = hi.y;
            }
#pragma unroll
            for (int na = 0; na < 4; na++) {
                int n = wn * 32 + na * 8 + q;
                uint2 b = *(const uint2*)&bs[ks * 1024 + n * 8 + r * 2];
#pragma unroll
                for (int ma = 0; ma < 2; ma++) mma_f16(D[ma][na], a[ma], b.x, b.y);
            }
        }
    }

    // ---- epilogue 2: write hh as bf16x2 ----
#pragma unroll
    for (int ma = 0; ma < 2; ma++) {
#pragma unroll
        for (int half = 0; half < 2; half++) {
            int row = rowblk + wm * 32 + ma * 16 + q + half * 8;
            if (row >= M) continue;
#pragma unroll
            for (int na = 0; na < 4; na++) {
                int ch = wn * 32 + na * 8 + 2 * r;
                out[(size_t)row * 64 + (ch >> 1)] =
                    pack_bf16x2(D[ma][na][half * 2 + 1], D[ma][na][half * 2]);
            }
        }
    }
}

// ============================================================================
// gather + finalize: warp per node, bf16 hh; cnt from CSR offsets
// ============================================================================
__global__ __launch_bounds__(256) void gather_finalize(const float* __restrict__ gcn_b,
                                                       float* __restrict__ out)
{
    int node = (blockIdx.x * blockDim.x + threadIdx.x) >> 5;
    int lane = threadIdx.x & 31;
    if (node >= N_NODES) return;
    int base = g_off[node];
    int cnt = g_off[node + 1] - base;
    float dgi = g_dg[node];

    const uint2* hh2 = (const uint2*)g_hhb;
    uint2 hv = hh2[(size_t)node * 32 + lane];
    float a0 = dgi * bf_lo(hv.x), a1 = dgi * bf_hi(hv.x);
    float a2 = dgi * bf_lo(hv.y), a3 = dgi * bf_hi(hv.y);

    for (int e0 = 0; e0 < cnt; e0 += 32) {
        int myidx = (e0 + lane < cnt) ? g_csr[base + e0 + lane] : 0;
        int lim = min(32, cnt - e0);
        int t = 0;
        for (; t + 4 <= lim; t += 4) {
            int s0 = __shfl_sync(0xffffffffu, myidx, t);
            int s1 = __shfl_sync(0xffffffffu, myidx, t + 1);
            int s2 = __shfl_sync(0xffffffffu, myidx, t + 2);
            int s3 = __shfl_sync(0xffffffffu, myidx, t + 3);
            float d0 = __ldg(g_dg + s0);
            float d1 = __ldg(g_dg + s1);
            float d2 = __ldg(g_dg + s2);
            float d3 = __ldg(g_dg + s3);
            uint2 v0 = __ldg(hh2 + (size_t)s0 * 32 + lane);
            uint2 v1 = __ldg(hh2 + (size_t)s1 * 32 + lane);
            uint2 v2 = __ldg(hh2 + (size_t)s2 * 32 + lane);
            uint2 v3 = __ldg(hh2 + (size_t)s3 * 32 + lane);
            a0 = fmaf(d0, bf_lo(v0.x), a0); a1 = fmaf(d0, bf_hi(v0.x), a1);
            a2 = fmaf(d0, bf_lo(v0.y), a2); a3 = fmaf(d0, bf_hi(v0.y), a3);
            a0 = fmaf(d1, bf_lo(v1.x), a0); a1 = fmaf(d1, bf_hi(v1.x), a1);
            a2 = fmaf(d1, bf_lo(v1.y), a2); a3 = fmaf(d1, bf_hi(v1.y), a3);
            a0 = fmaf(d2, bf_lo(v2.x), a0); a1 = fmaf(d2, bf_hi(v2.x), a1);
            a2 = fmaf(d2, bf_lo(v2.y), a2); a3 = fmaf(d2, bf_hi(v2.y), a3);
            a0 = fmaf(d3, bf_lo(v3.x), a0); a1 = fmaf(d3, bf_hi(v3.x), a1);
            a2 = fmaf(d3, bf_lo(v3.y), a2); a3 = fmaf(d3, bf_hi(v3.y), a3);
        }
        for (; t < lim; t++) {
            int s = __shfl_sync(0xffffffffu, myidx, t);
            float ds = __ldg(g_dg + s);
            uint2 v = __ldg(hh2 + (size_t)s * 32 + lane);
            a0 = fmaf(ds, bf_lo(v.x), a0);
            a1 = fmaf(ds, bf_hi(v.x), a1);
            a2 = fmaf(ds, bf_lo(v.y), a2);
            a3 = fmaf(ds, bf_hi(v.y), a3);
        }
    }

    float4 gb = ((const float4*)gcn_b)[lane];
    float4 fa = ((const float4*)g_fa)[lane];
    float sum = fmaxf(dgi * a0 + gb.x, 0.0f) * fa.x
              + fmaxf(dgi * a1 + gb.y, 0.0f) * fa.y
              + fmaxf(dgi * a2 + gb.z, 0.0f) * fa.z
              + fmaxf(dgi * a3 + gb.w, 0.0f) * fa.w;
#pragma unroll
    for (int o = 16; o > 0; o >>= 1) sum += __shfl_down_sync(0xffffffffu, sum, o);
    if (lane == 0) out[node] = sum + g_fc;
}

// ============================================================================
// launch. gemm_fused stays the 4th launched kernel for ncu capture.
// ============================================================================
extern "C" void kernel_launch(void* const* d_in, const int* in_sizes, int n_in,
                              void* d_out, int out_size)
{
    const float* x        = (const float*)d_in[0];
    const int*   ei       = (const int*)  d_in[1];
    const float* W_x      = (const float*)d_in[3];
    const float* w_c      = (const float*)d_in[4];
    const float* b        = (const float*)d_in[5];
    const float* theta_b  = (const float*)d_in[7];
    const float* gcn_w    = (const float*)d_in[8];
    const float* gcn_b    = (const float*)d_in[9];
    const float* bn_gamma = (const float*)d_in[10];
    const float* bn_beta  = (const float*)d_in[11];
    const float* bn_mean  = (const float*)d_in[12];
    const float* bn_var   = (const float*)d_in[13];
    const float* lin_w    = (const float*)d_in[14];
    const float* lin_b    = (const float*)d_in[15];
    float* out = (float*)d_out;

    const int* src = ei;
    const int* dst = ei + N_EDGES;

    const int SMF = SMU * 4;  // 67584 B

    static cudaStream_t s1 = nullptr;
    static cudaEvent_t evRoot, evCsr;
    if (!s1) {
        cudaStreamCreateWithFlags(&s1, cudaStreamNonBlocking);
        cudaEventCreateWithFlags(&evRoot, cudaEventDisableTiming);
        cudaEventCreateWithFlags(&evCsr,  cudaEventDisableTiming);
        cudaFuncSetAttribute((const void*)gemm_fused,
                             cudaFuncAttributeMaxDynamicSharedMemorySize, SMF);
    }

    uint32_t *hhp, *wcp;
    cudaGetSymbolAddress((void**)&hhp, g_hhb);
    cudaGetSymbolAddress((void**)&wcp, g_Wc);

    // fork s1 from main at graph root
    cudaEventRecord(evRoot, 0);
    cudaStreamWaitEvent(s1, evRoot, 0);

    prep_all<<<129, 256>>>(W_x, gcn_w, theta_b, b, w_c,                 // #1 (main)
                           bn_gamma, bn_beta, bn_mean, bn_var, lin_w, lin_b);
    count_kernel<<<(N_EDGES + 255) / 256, 256, 0, s1>>>(dst);           // #2 (s1)
    scan_a<<<NB, 256, 0, s1>>>();                                       // #3 (s1)
    gemm_fused<<<(N_NODES + 63) / 64, 256, SMF>>>(x, wcp, hhp, N_NODES); // #4 (main)
    scan_bc<<<NB, 256, 0, s1>>>();                                      // #5 (s1)
    fill_kernel<<<(N_EDGES + 255) / 256, 256, 0, s1>>>(src, dst);       // #6 (s1)
    cudaEventRecord(evCsr, s1);

    // join: gather needs gemm (stream order) + CSR (event)
    cudaStreamWaitEvent(0, evCsr, 0);
    gather_finalize<<<(N_NODES * 32 + 255) / 256, 256>>>(gcn_b, out);   // #7 (main)
}